// round 13
// baseline (speedup 1.0000x reference)
#include <cuda_runtime.h>
#include <cuda_fp16.h>
#include <cstdint>

#define BDIM 16384
#define INDIM 2048
#define OUTDIM 2048

// ---------------- scratch (static device globals; no allocation) ----------------
__device__ __half g_xh[(size_t)BDIM * INDIM];    // x in fp16
__device__ __half g_wh[(size_t)OUTDIM * INDIM];  // sign(W) in fp16 (+1/-1 exact)
__device__ __half g_yh[(size_t)BDIM * OUTDIM];   // y intermediate in fp16
__device__ float  g_cs[OUTDIM];                  // column sums of y
__device__ float  g_cq[OUTDIM];                  // column sums of y^2
__device__ float  g_scale[OUTDIM];
__device__ float  g_bias[OUTDIM];

// ---------------- helpers ----------------
__device__ __forceinline__ uint32_t smem_u32(const void* p) {
    uint32_t a;
    asm("{ .reg .u64 t; cvta.to.shared.u64 t, %1; cvt.u32.u64 %0, t; }" : "=r"(a) : "l"(p));
    return a;
}
__device__ __forceinline__ void cp16(uint32_t s, const void* g) {
    asm volatile("cp.async.cg.shared.global [%0], [%1], 16;" :: "r"(s), "l"(g) : "memory");
}
#define CP_COMMIT() asm volatile("cp.async.commit_group;" ::: "memory")
#define CP_WAIT(n)  asm volatile("cp.async.wait_group %0;" :: "n"(n) : "memory")

__device__ __forceinline__ void ldsm_x4(uint32_t* r, uint32_t addr) {
    asm volatile("ldmatrix.sync.aligned.m8n8.x4.shared.b16 {%0,%1,%2,%3}, [%4];"
                 : "=r"(r[0]), "=r"(r[1]), "=r"(r[2]), "=r"(r[3]) : "r"(addr));
}
__device__ __forceinline__ void mma16816(float* c, const uint32_t* a, const uint32_t* b) {
    asm volatile(
        "mma.sync.aligned.m16n8k16.row.col.f32.f16.f16.f32 "
        "{%0,%1,%2,%3}, {%4,%5,%6,%7}, {%8,%9}, {%0,%1,%2,%3};"
        : "+f"(c[0]), "+f"(c[1]), "+f"(c[2]), "+f"(c[3])
        : "r"(a[0]), "r"(a[1]), "r"(a[2]), "r"(a[3]), "r"(b[0]), "r"(b[1]));
}

// ---------------- conversion kernels ----------------
__global__ void k_convert_x(const float* __restrict__ x) {
    int i = blockIdx.x * blockDim.x + threadIdx.x;   // over 8388608 float4s
    float4 v = ((const float4*)x)[i];
    ((__half2*)g_xh)[2 * (size_t)i]     = __floats2half2_rn(v.x, v.y);
    ((__half2*)g_xh)[2 * (size_t)i + 1] = __floats2half2_rn(v.z, v.w);
}

__global__ void k_convert_w(const float* __restrict__ w) {
    int i = blockIdx.x * blockDim.x + threadIdx.x;   // over 1048576 float4s
    float4 v = ((const float4*)w)[i];
    float s0 = (v.x >= 0.f) ? 1.f : -1.f;
    float s1 = (v.y >= 0.f) ? 1.f : -1.f;
    float s2 = (v.z >= 0.f) ? 1.f : -1.f;
    float s3 = (v.w >= 0.f) ? 1.f : -1.f;
    ((__half2*)g_wh)[2 * (size_t)i]     = __floats2half2_rn(s0, s1);
    ((__half2*)g_wh)[2 * (size_t)i + 1] = __floats2half2_rn(s2, s3);
    if (i < OUTDIM) { g_cs[i] = 0.f; g_cq[i] = 0.f; }   // reset stats every call
}

// ---------------- HMMA GEMM: y_fp16 = x_fp16 @ sign(W)^T ----------------
// CTA tile 128x128, BK=32, 4 cp.async stages, 8 warps (warp tile 32x64).
static constexpr int BM = 128, BN = 128, BK = 32;
static constexpr int STAGES = 4;
static constexpr int NK = INDIM / BK;                 // 64
static constexpr int TILE_BYTES = BM * BK * 2;        // 8192 per operand
static constexpr int STAGE_BYTES = 2 * TILE_BYTES;    // 16384
static constexpr int DSMEM = STAGES * STAGE_BYTES;    // 65536

// swizzled smem offset for (row, 16B-chunk c) in a 128row x 64B tile
__device__ __forceinline__ uint32_t swz(int r, int c) {
    return (uint32_t)(r * 64 + ((c ^ (r & 3)) << 4));
}

__device__ __forceinline__ void load_tile_pair(uint32_t sbase, const __half* gA,
                                               const __half* gB, int tid) {
    #pragma unroll
    for (int h = 0; h < 2; h++) {
        int idx = tid + h * 256;                      // 512 x 16B chunks per operand
        int r = idx >> 2, c = idx & 3;
        cp16(sbase + swz(r, c), gA + (size_t)r * INDIM + c * 8);
        cp16(sbase + TILE_BYTES + swz(r, c), gB + (size_t)r * INDIM + c * 8);
    }
}

__global__ void __launch_bounds__(256, 2) k_gemm() {
    extern __shared__ char dsm[];
    const uint32_t sb = smem_u32(dsm);

    const int tid = threadIdx.x;
    const int wid = tid >> 5, lane = tid & 31;
    const int wm = wid & 3, wn = wid >> 2;            // 4 x 2 warp grid
    const int warp_m0 = wm * 32, warp_n0 = wn * 64;

    // L2-friendly mapping: 16 consecutive bids share the same m-block
    const int m0 = (int)(blockIdx.x >> 4) * BM;
    const int n0 = (int)(blockIdx.x & 15) * BN;

    const __half* gA0 = g_xh + (size_t)m0 * INDIM;
    const __half* gB0 = g_wh + (size_t)n0 * INDIM;

    // per-lane ldmatrix offsets (within a stage)
    uint32_t a_off[2][2];
    #pragma unroll
    for (int mt = 0; mt < 2; mt++)
        #pragma unroll
        for (int ks = 0; ks < 2; ks++) {
            int r = warp_m0 + mt * 16 + (lane & 15);
            int c = ks * 2 + (lane >> 4);
            a_off[mt][ks] = swz(r, c);
        }
    uint32_t b_off[4][2];
    #pragma unroll
    for (int nt = 0; nt < 4; nt++)
        #pragma unroll
        for (int ks = 0; ks < 2; ks++) {
            int r = warp_n0 + nt * 16 + ((lane >> 4) << 3) + (lane & 7);
            int c = ks * 2 + ((lane >> 3) & 1);
            b_off[nt][ks] = (uint32_t)TILE_BYTES + swz(r, c);
        }

    float acc[2][8][4];
    #pragma unroll
    for (int mt = 0; mt < 2; mt++)
        #pragma unroll
        for (int nt = 0; nt < 8; nt++)
            #pragma unroll
            for (int j = 0; j < 4; j++) acc[mt][nt][j] = 0.f;

    // prologue: stages 0..STAGES-2
    #pragma unroll
    for (int s = 0; s < STAGES - 1; s++) {
        load_tile_pair(sb + s * STAGE_BYTES, gA0 + s * BK, gB0 + s * BK, tid);
        CP_COMMIT();
    }

    for (int kt = 0; kt < NK; kt++) {
        CP_WAIT(STAGES - 2);
        __syncthreads();

        int pf = kt + STAGES - 1;
        if (pf < NK)
            load_tile_pair(sb + (pf % STAGES) * STAGE_BYTES,
                           gA0 + pf * BK, gB0 + pf * BK, tid);
        CP_COMMIT();

        const uint32_t st = sb + (kt % STAGES) * STAGE_BYTES;
        #pragma unroll
        for (int ks = 0; ks < 2; ks++) {
            uint32_t a[2][4], b[4][4];
            #pragma unroll
            for (int mt = 0; mt < 2; mt++) ldsm_x4(a[mt], st + a_off[mt][ks]);
            #pragma unroll
            for (int nt = 0; nt < 4; nt++) ldsm_x4(b[nt], st + b_off[nt][ks]);
            #pragma unroll
            for (int mt = 0; mt < 2; mt++)
                #pragma unroll
                for (int nt = 0; nt < 4; nt++) {
                    mma16816(acc[mt][2 * nt],     a[mt], &b[nt][0]);
                    mma16816(acc[mt][2 * nt + 1], a[mt], &b[nt][2]);
                }
        }
    }

    // ---- plain epilogue: write y in fp16, fire-and-forget, no barriers ----
    const int g = lane >> 2, tg = lane & 3;
    #pragma unroll
    for (int mt = 0; mt < 2; mt++) {
        int mrow = m0 + warp_m0 + mt * 16 + g;
        #pragma unroll
        for (int nt = 0; nt < 8; nt++) {
            int col = n0 + warp_n0 + nt * 8 + tg * 2;
            __half2* p0 = (__half2*)(g_yh + (size_t)mrow * OUTDIM + col);
            __half2* p1 = (__half2*)(g_yh + (size_t)(mrow + 8) * OUTDIM + col);
            *p0 = __floats2half2_rn(acc[mt][nt][0], acc[mt][nt][1]);
            *p1 = __floats2half2_rn(acc[mt][nt][2], acc[mt][nt][3]);
        }
    }
}

// ---------------- BN statistics over fp16 y: wide grid, high occupancy ----------------
// 512 blocks x 32 rows; each thread owns 8 columns (one 16B chunk per row).
__global__ void k_stats(void) {
    int t = threadIdx.x;
    int r0 = blockIdx.x * 32;
    float s[8], q[8];
    #pragma unroll
    for (int j = 0; j < 8; j++) { s[j] = 0.f; q[j] = 0.f; }
    const uint4* p = (const uint4*)(g_yh + (size_t)r0 * OUTDIM) + t;
    #pragma unroll 4
    for (int r = 0; r < 32; r++) {
        uint4 v = p[(size_t)r * (OUTDIM / 8)];
        const uint32_t u[4] = {v.x, v.y, v.z, v.w};
        #pragma unroll
        for (int j = 0; j < 4; j++) {
            float2 f = __half22float2(*(const __half2*)&u[j]);
            s[2 * j]     += f.x;  q[2 * j]     += f.x * f.x;
            s[2 * j + 1] += f.y;  q[2 * j + 1] += f.y * f.y;
        }
    }
    int c0 = t * 8;
    #pragma unroll
    for (int j = 0; j < 8; j++) {
        atomicAdd(&g_cs[c0 + j], s[j]);
        atomicAdd(&g_cq[c0 + j], q[j]);
    }
}

__global__ void k_params(const float* __restrict__ gamma, const float* __restrict__ beta) {
    int o = blockIdx.x * blockDim.x + threadIdx.x;
    if (o < OUTDIM) {
        float inv_n = 1.f / (float)BDIM;
        float mean = g_cs[o] * inv_n;
        float var  = g_cq[o] * inv_n - mean * mean;
        float sc = gamma[o] * rsqrtf(var + 1e-5f);
        g_scale[o] = sc;
        g_bias[o]  = beta[o] - mean * sc;
    }
}

// ---------------- normalize + ReLU: fp16 y -> fp32 out ----------------
__global__ void k_norm(float* __restrict__ out) {
    int i = blockIdx.x * blockDim.x + threadIdx.x;   // over 4194304 8-col chunks
    int c8 = i & (OUTDIM / 8 - 1);
    uint4 v = ((const uint4*)g_yh)[i];
    const uint32_t u[4] = {v.x, v.y, v.z, v.w};
    float4 sc0 = ((const float4*)g_scale)[2 * c8];
    float4 sc1 = ((const float4*)g_scale)[2 * c8 + 1];
    float4 bs0 = ((const float4*)g_bias)[2 * c8];
    float4 bs1 = ((const float4*)g_bias)[2 * c8 + 1];
    float2 f0 = __half22float2(*(const __half2*)&u[0]);
    float2 f1 = __half22float2(*(const __half2*)&u[1]);
    float2 f2 = __half22float2(*(const __half2*)&u[2]);
    float2 f3 = __half22float2(*(const __half2*)&u[3]);
    float4 o0, o1;
    o0.x = fmaxf(fmaf(f0.x, sc0.x, bs0.x), 0.f);
    o0.y = fmaxf(fmaf(f0.y, sc0.y, bs0.y), 0.f);
    o0.z = fmaxf(fmaf(f1.x, sc0.z, bs0.z), 0.f);
    o0.w = fmaxf(fmaf(f1.y, sc0.w, bs0.w), 0.f);
    o1.x = fmaxf(fmaf(f2.x, sc1.x, bs1.x), 0.f);
    o1.y = fmaxf(fmaf(f2.y, sc1.y, bs1.y), 0.f);
    o1.z = fmaxf(fmaf(f3.x, sc1.z, bs1.z), 0.f);
    o1.w = fmaxf(fmaf(f3.y, sc1.w, bs1.w), 0.f);
    ((float4*)out)[2 * (size_t)i]     = o0;
    ((float4*)out)[2 * (size_t)i + 1] = o1;
}

// ---------------- launch ----------------
extern "C" void kernel_launch(void* const* d_in, const int* in_sizes, int n_in,
                              void* d_out, int out_size) {
    const float* x     = (const float*)d_in[0];
    const float* w     = (const float*)d_in[1];
    const float* gamma = (const float*)d_in[2];
    const float* beta  = (const float*)d_in[3];
    float* out = (float*)d_out;

    static bool attr_set = false;
    if (!attr_set) {
        cudaFuncSetAttribute(k_gemm, cudaFuncAttributeMaxDynamicSharedMemorySize, DSMEM);
        attr_set = true;
    }

    k_convert_x<<<(BDIM * INDIM / 4) / 256, 256>>>(x);
    k_convert_w<<<(OUTDIM * INDIM / 4) / 256, 256>>>(w);

    k_gemm<<<(BDIM / BM) * (OUTDIM / BN), 256, DSMEM>>>();

    k_stats<<<BDIM / 32, 256>>>();
    k_params<<<(OUTDIM + 255) / 256, 256>>>(gamma, beta);
    k_norm<<<(BDIM * OUTDIM / 8) / 256, 256>>>(out);
}

// round 14
// speedup vs baseline: 1.0537x; 1.0537x over previous
#include <cuda_runtime.h>
#include <cuda_fp16.h>
#include <cstdint>

#define BDIM 16384
#define INDIM 2048
#define OUTDIM 2048

// ---------------- scratch (static device globals; no allocation) ----------------
__device__ __half g_xh[(size_t)BDIM * INDIM];    // x in fp16
__device__ __half g_wh[(size_t)OUTDIM * INDIM];  // sign(W) in fp16 (+1/-1 exact)
__device__ __half g_yh[(size_t)BDIM * OUTDIM];   // y intermediate in fp16
__device__ float  g_cs[OUTDIM];                  // column sums of y
__device__ float  g_cq[OUTDIM];                  // column sums of y^2
__device__ float  g_scale[OUTDIM];
__device__ float  g_bias[OUTDIM];

// ---------------- helpers ----------------
__device__ __forceinline__ uint32_t smem_u32(const void* p) {
    uint32_t a;
    asm("{ .reg .u64 t; cvta.to.shared.u64 t, %1; cvt.u32.u64 %0, t; }" : "=r"(a) : "l"(p));
    return a;
}
__device__ __forceinline__ void cp16(uint32_t s, const void* g) {
    asm volatile("cp.async.cg.shared.global [%0], [%1], 16;" :: "r"(s), "l"(g) : "memory");
}
#define CP_COMMIT() asm volatile("cp.async.commit_group;" ::: "memory")
#define CP_WAIT(n)  asm volatile("cp.async.wait_group %0;" :: "n"(n) : "memory")

__device__ __forceinline__ void ldsm_x4(uint32_t* r, uint32_t addr) {
    asm volatile("ldmatrix.sync.aligned.m8n8.x4.shared.b16 {%0,%1,%2,%3}, [%4];"
                 : "=r"(r[0]), "=r"(r[1]), "=r"(r[2]), "=r"(r[3]) : "r"(addr));
}
__device__ __forceinline__ void mma16816(float* c, const uint32_t* a, const uint32_t* b) {
    asm volatile(
        "mma.sync.aligned.m16n8k16.row.col.f32.f16.f16.f32 "
        "{%0,%1,%2,%3}, {%4,%5,%6,%7}, {%8,%9}, {%0,%1,%2,%3};"
        : "+f"(c[0]), "+f"(c[1]), "+f"(c[2]), "+f"(c[3])
        : "r"(a[0]), "r"(a[1]), "r"(a[2]), "r"(a[3]), "r"(b[0]), "r"(b[1]));
}

// ---------------- conversion kernels ----------------
__global__ void k_convert_x(const float* __restrict__ x) {
    int i = blockIdx.x * blockDim.x + threadIdx.x;   // over 8388608 float4s
    float4 v = ((const float4*)x)[i];
    ((__half2*)g_xh)[2 * (size_t)i]     = __floats2half2_rn(v.x, v.y);
    ((__half2*)g_xh)[2 * (size_t)i + 1] = __floats2half2_rn(v.z, v.w);
}

__global__ void k_convert_w(const float* __restrict__ w) {
    int i = blockIdx.x * blockDim.x + threadIdx.x;   // over 1048576 float4s
    float4 v = ((const float4*)w)[i];
    float s0 = (v.x >= 0.f) ? 1.f : -1.f;
    float s1 = (v.y >= 0.f) ? 1.f : -1.f;
    float s2 = (v.z >= 0.f) ? 1.f : -1.f;
    float s3 = (v.w >= 0.f) ? 1.f : -1.f;
    ((__half2*)g_wh)[2 * (size_t)i]     = __floats2half2_rn(s0, s1);
    ((__half2*)g_wh)[2 * (size_t)i + 1] = __floats2half2_rn(s2, s3);
    if (i < OUTDIM) { g_cs[i] = 0.f; g_cq[i] = 0.f; }   // reset stats every call
}

// ---------------- HMMA GEMM + fused BN stats (y stored fp16) ----------------
// CTA tile 128x128, BK=32, 4 cp.async stages, 8 warps (warp tile 32x64).
static constexpr int BM = 128, BN = 128, BK = 32;
static constexpr int STAGES = 4;
static constexpr int NK = INDIM / BK;                 // 64
static constexpr int TILE_BYTES = BM * BK * 2;        // 8192 per operand
static constexpr int STAGE_BYTES = 2 * TILE_BYTES;    // 16384
static constexpr int DSMEM = STAGES * STAGE_BYTES;    // 65536

// swizzled smem offset for (row, 16B-chunk c) in a 128row x 64B tile
__device__ __forceinline__ uint32_t swz(int r, int c) {
    return (uint32_t)(r * 64 + ((c ^ (r & 3)) << 4));
}

__device__ __forceinline__ void load_tile_pair(uint32_t sbase, const __half* gA,
                                               const __half* gB, int tid) {
    #pragma unroll
    for (int h = 0; h < 2; h++) {
        int idx = tid + h * 256;                      // 512 x 16B chunks per operand
        int r = idx >> 2, c = idx & 3;
        cp16(sbase + swz(r, c), gA + (size_t)r * INDIM + c * 8);
        cp16(sbase + TILE_BYTES + swz(r, c), gB + (size_t)r * INDIM + c * 8);
    }
}

__global__ void __launch_bounds__(256, 2) k_gemm() {
    extern __shared__ char dsm[];
    const uint32_t sb = smem_u32(dsm);

    const int tid = threadIdx.x;
    const int wid = tid >> 5, lane = tid & 31;
    const int wm = wid & 3, wn = wid >> 2;            // 4 x 2 warp grid
    const int warp_m0 = wm * 32, warp_n0 = wn * 64;

    // L2-friendly mapping: 16 consecutive bids share the same m-block
    const int m0 = (int)(blockIdx.x >> 4) * BM;
    const int n0 = (int)(blockIdx.x & 15) * BN;

    const __half* gA0 = g_xh + (size_t)m0 * INDIM;
    const __half* gB0 = g_wh + (size_t)n0 * INDIM;

    // per-lane ldmatrix offsets (within a stage)
    uint32_t a_off[2][2];
    #pragma unroll
    for (int mt = 0; mt < 2; mt++)
        #pragma unroll
        for (int ks = 0; ks < 2; ks++) {
            int r = warp_m0 + mt * 16 + (lane & 15);
            int c = ks * 2 + (lane >> 4);
            a_off[mt][ks] = swz(r, c);
        }
    uint32_t b_off[4][2];
    #pragma unroll
    for (int nt = 0; nt < 4; nt++)
        #pragma unroll
        for (int ks = 0; ks < 2; ks++) {
            int r = warp_n0 + nt * 16 + ((lane >> 4) << 3) + (lane & 7);
            int c = ks * 2 + ((lane >> 3) & 1);
            b_off[nt][ks] = (uint32_t)TILE_BYTES + swz(r, c);
        }

    float acc[2][8][4];
    #pragma unroll
    for (int mt = 0; mt < 2; mt++)
        #pragma unroll
        for (int nt = 0; nt < 8; nt++)
            #pragma unroll
            for (int j = 0; j < 4; j++) acc[mt][nt][j] = 0.f;

    // prologue: stages 0..STAGES-2
    #pragma unroll
    for (int s = 0; s < STAGES - 1; s++) {
        load_tile_pair(sb + s * STAGE_BYTES, gA0 + s * BK, gB0 + s * BK, tid);
        CP_COMMIT();
    }

    for (int kt = 0; kt < NK; kt++) {
        CP_WAIT(STAGES - 2);
        __syncthreads();

        int pf = kt + STAGES - 1;
        if (pf < NK)
            load_tile_pair(sb + (pf % STAGES) * STAGE_BYTES,
                           gA0 + pf * BK, gB0 + pf * BK, tid);
        CP_COMMIT();

        const uint32_t st = sb + (kt % STAGES) * STAGE_BYTES;
        #pragma unroll
        for (int ks = 0; ks < 2; ks++) {
            uint32_t a[2][4], b[4][4];
            #pragma unroll
            for (int mt = 0; mt < 2; mt++) ldsm_x4(a[mt], st + a_off[mt][ks]);
            #pragma unroll
            for (int nt = 0; nt < 4; nt++) ldsm_x4(b[nt], st + b_off[nt][ks]);
            #pragma unroll
            for (int mt = 0; mt < 2; mt++)
                #pragma unroll
                for (int nt = 0; nt < 4; nt++) {
                    mma16816(acc[mt][2 * nt],     a[mt], &b[nt][0]);
                    mma16816(acc[mt][2 * nt + 1], a[mt], &b[nt][2]);
                }
        }
    }
    CP_WAIT(0);          // retire trailing (empty) cp groups before smem reuse

    // ---- fused BN statistics, register-flat ----
    __syncthreads();
    float* sred = (float*)dsm;               // reuse pipeline smem: [8][64][2]
    #pragma unroll
    for (int nt = 0; nt < 8; nt++) {
        float e = 0.f, o = 0.f, x2e = 0.f, x2o = 0.f;
        #pragma unroll
        for (int mt = 0; mt < 2; mt++) {
            float a0 = acc[mt][nt][0], a1 = acc[mt][nt][1];
            float a2 = acc[mt][nt][2], a3 = acc[mt][nt][3];
            e += a0 + a2;  o += a1 + a3;
            x2e += a0 * a0 + a2 * a2;  x2o += a1 * a1 + a3 * a3;
        }
        #pragma unroll
        for (int d = 16; d >= 4; d >>= 1) {   // reduce over the 8 g-lanes
            e   += __shfl_xor_sync(0xffffffff, e, d);
            o   += __shfl_xor_sync(0xffffffff, o, d);
            x2e += __shfl_xor_sync(0xffffffff, x2e, d);
            x2o += __shfl_xor_sync(0xffffffff, x2o, d);
        }
        if (lane < 4) {                       // lane == tg, g == 0
            int lc = nt * 8 + lane * 2;
            sred[(wid * 64 + lc) * 2 + 0]     = e;
            sred[(wid * 64 + lc) * 2 + 1]     = x2e;
            sred[(wid * 64 + lc + 1) * 2 + 0] = o;
            sred[(wid * 64 + lc + 1) * 2 + 1] = x2o;
        }
    }
    __syncthreads();

    // cross-warp reduce (4 wm-warps share each column) + one atomic per col/stat
    {
        int col = tid >> 1, stt = tid & 1;   // 128 cols x 2 stats
        int wbase = (col >> 6) * 4, lc = col & 63;
        float v = sred[((wbase + 0) * 64 + lc) * 2 + stt]
                + sred[((wbase + 1) * 64 + lc) * 2 + stt]
                + sred[((wbase + 2) * 64 + lc) * 2 + stt]
                + sred[((wbase + 3) * 64 + lc) * 2 + stt];
        atomicAdd((stt ? g_cq : g_cs) + n0 + col, v);
    }

    // ---- y-write last, in fp16 (half the store traffic), no barrier after ----
    const int g = lane >> 2, tg = lane & 3;
    #pragma unroll
    for (int mt = 0; mt < 2; mt++) {
        int mrow = m0 + warp_m0 + mt * 16 + g;
        #pragma unroll
        for (int nt = 0; nt < 8; nt++) {
            int col = n0 + warp_n0 + nt * 8 + tg * 2;
            __half2* p0 = (__half2*)(g_yh + (size_t)mrow * OUTDIM + col);
            __half2* p1 = (__half2*)(g_yh + (size_t)(mrow + 8) * OUTDIM + col);
            *p0 = __floats2half2_rn(acc[mt][nt][0], acc[mt][nt][1]);
            *p1 = __floats2half2_rn(acc[mt][nt][2], acc[mt][nt][3]);
        }
    }
}

__global__ void k_params(const float* __restrict__ gamma, const float* __restrict__ beta) {
    int o = blockIdx.x * blockDim.x + threadIdx.x;
    if (o < OUTDIM) {
        float inv_n = 1.f / (float)BDIM;
        float mean = g_cs[o] * inv_n;
        float var  = g_cq[o] * inv_n - mean * mean;
        float sc = gamma[o] * rsqrtf(var + 1e-5f);
        g_scale[o] = sc;
        g_bias[o]  = beta[o] - mean * sc;
    }
}

// ---------------- normalize + ReLU: fp16 y -> fp32 out ----------------
__global__ void k_norm(float* __restrict__ out) {
    int i = blockIdx.x * blockDim.x + threadIdx.x;   // over 4194304 8-col chunks
    int c8 = i & (OUTDIM / 8 - 1);
    uint4 v = ((const uint4*)g_yh)[i];
    const uint32_t u[4] = {v.x, v.y, v.z, v.w};
    float4 sc0 = ((const float4*)g_scale)[2 * c8];
    float4 sc1 = ((const float4*)g_scale)[2 * c8 + 1];
    float4 bs0 = ((const float4*)g_bias)[2 * c8];
    float4 bs1 = ((const float4*)g_bias)[2 * c8 + 1];
    float2 f0 = __half22float2(*(const __half2*)&u[0]);
    float2 f1 = __half22float2(*(const __half2*)&u[1]);
    float2 f2 = __half22float2(*(const __half2*)&u[2]);
    float2 f3 = __half22float2(*(const __half2*)&u[3]);
    float4 o0, o1;
    o0.x = fmaxf(fmaf(f0.x, sc0.x, bs0.x), 0.f);
    o0.y = fmaxf(fmaf(f0.y, sc0.y, bs0.y), 0.f);
    o0.z = fmaxf(fmaf(f1.x, sc0.z, bs0.z), 0.f);
    o0.w = fmaxf(fmaf(f1.y, sc0.w, bs0.w), 0.f);
    o1.x = fmaxf(fmaf(f2.x, sc1.x, bs1.x), 0.f);
    o1.y = fmaxf(fmaf(f2.y, sc1.y, bs1.y), 0.f);
    o1.z = fmaxf(fmaf(f3.x, sc1.z, bs1.z), 0.f);
    o1.w = fmaxf(fmaf(f3.y, sc1.w, bs1.w), 0.f);
    ((float4*)out)[2 * (size_t)i]     = o0;
    ((float4*)out)[2 * (size_t)i + 1] = o1;
}

// ---------------- launch ----------------
extern "C" void kernel_launch(void* const* d_in, const int* in_sizes, int n_in,
                              void* d_out, int out_size) {
    const float* x     = (const float*)d_in[0];
    const float* w     = (const float*)d_in[1];
    const float* gamma = (const float*)d_in[2];
    const float* beta  = (const float*)d_in[3];
    float* out = (float*)d_out;

    static bool attr_set = false;
    if (!attr_set) {
        cudaFuncSetAttribute(k_gemm, cudaFuncAttributeMaxDynamicSharedMemorySize, DSMEM);
        attr_set = true;
    }

    k_convert_x<<<(BDIM * INDIM / 4) / 256, 256>>>(x);
    k_convert_w<<<(OUTDIM * INDIM / 4) / 256, 256>>>(w);

    k_gemm<<<(BDIM / BM) * (OUTDIM / BN), 256, DSMEM>>>();

    k_params<<<(OUTDIM + 255) / 256, 256>>>(gamma, beta);
    k_norm<<<(BDIM * OUTDIM / 8) / 256, 256>>>(out);
}

// round 16
// speedup vs baseline: 1.4382x; 1.3650x over previous
#include <cuda_runtime.h>
#include <cuda_fp16.h>
#include <cstdint>

#define BDIM 16384
#define INDIM 2048
#define OUTDIM 2048

// ---------------- scratch (static device globals; no allocation) ----------------
__device__ __half g_xh[(size_t)BDIM * INDIM];    // x in fp16
__device__ __half g_wh[(size_t)OUTDIM * INDIM];  // sign(W) in fp16 (+1/-1 exact)
__device__ __half g_yh[(size_t)BDIM * OUTDIM];   // y intermediate in fp16
__device__ float  g_cs[OUTDIM];                  // column sums of y
__device__ float  g_cq[OUTDIM];                  // column sums of y^2
__device__ float  g_scale[OUTDIM];
__device__ float  g_bias[OUTDIM];

// ---------------- helpers ----------------
__device__ __forceinline__ uint32_t smem_u32(const void* p) {
    uint32_t a;
    asm("{ .reg .u64 t; cvta.to.shared.u64 t, %1; cvt.u32.u64 %0, t; }" : "=r"(a) : "l"(p));
    return a;
}
__device__ __forceinline__ void cp16(uint32_t s, const void* g) {
    asm volatile("cp.async.cg.shared.global [%0], [%1], 16;" :: "r"(s), "l"(g) : "memory");
}
#define CP_COMMIT() asm volatile("cp.async.commit_group;" ::: "memory")
#define CP_WAIT(n)  asm volatile("cp.async.wait_group %0;" :: "n"(n) : "memory")

__device__ __forceinline__ void ldsm_x4(uint32_t* r, uint32_t addr) {
    asm volatile("ldmatrix.sync.aligned.m8n8.x4.shared.b16 {%0,%1,%2,%3}, [%4];"
                 : "=r"(r[0]), "=r"(r[1]), "=r"(r[2]), "=r"(r[3]) : "r"(addr));
}
__device__ __forceinline__ void mma16816(float* c, const uint32_t* a, const uint32_t* b) {
    asm volatile(
        "mma.sync.aligned.m16n8k16.row.col.f32.f16.f16.f32 "
        "{%0,%1,%2,%3}, {%4,%5,%6,%7}, {%8,%9}, {%0,%1,%2,%3};"
        : "+f"(c[0]), "+f"(c[1]), "+f"(c[2]), "+f"(c[3])
        : "r"(a[0]), "r"(a[1]), "r"(a[2]), "r"(a[3]), "r"(b[0]), "r"(b[1]));
}

// ---------------- conversion kernels ----------------
__global__ void k_convert_x(const float* __restrict__ x) {
    int i = blockIdx.x * blockDim.x + threadIdx.x;   // over 8388608 float4s
    float4 v = ((const float4*)x)[i];
    ((__half2*)g_xh)[2 * (size_t)i]     = __floats2half2_rn(v.x, v.y);
    ((__half2*)g_xh)[2 * (size_t)i + 1] = __floats2half2_rn(v.z, v.w);
}

__global__ void k_convert_w(const float* __restrict__ w) {
    int i = blockIdx.x * blockDim.x + threadIdx.x;   // over 1048576 float4s
    float4 v = ((const float4*)w)[i];
    float s0 = (v.x >= 0.f) ? 1.f : -1.f;
    float s1 = (v.y >= 0.f) ? 1.f : -1.f;
    float s2 = (v.z >= 0.f) ? 1.f : -1.f;
    float s3 = (v.w >= 0.f) ? 1.f : -1.f;
    ((__half2*)g_wh)[2 * (size_t)i]     = __floats2half2_rn(s0, s1);
    ((__half2*)g_wh)[2 * (size_t)i + 1] = __floats2half2_rn(s2, s3);
    if (i < OUTDIM) { g_cs[i] = 0.f; g_cq[i] = 0.f; }   // reset stats every call
}

// ---------------- HMMA GEMM + fused BN stats (y stored fp16) ----------------
// CTA tile 128x128, BK=32, 4 cp.async stages, 8 warps (warp tile 32x64).
static constexpr int BM = 128, BN = 128, BK = 32;
static constexpr int STAGES = 4;
static constexpr int NK = INDIM / BK;                 // 64
static constexpr int TILE_BYTES = BM * BK * 2;        // 8192 per operand
static constexpr int STAGE_BYTES = 2 * TILE_BYTES;    // 16384
static constexpr int DSMEM = STAGES * STAGE_BYTES;    // 65536

// swizzled smem offset for (row, 16B-chunk c) in a 128row x 64B tile.
// Row stride 64B = 16 banks, so rows r and r+2 share a bank-start; an ldmatrix
// phase touches 8 consecutive rows of one chunk column. Permuting on (r>>1)&3
// gives even rows {0,2,4,6} four DISTINCT chunk slots (banks 0-15) and odd rows
// {1,3,5,7} the same at +16 banks -> all 32 banks hit once -> conflict-free.
// (The old r&3 permutation collided rows 0/4, 2/6, 1/5, 3/7: 2-way conflict on
// every ldmatrix phase and thus ~2x fragment-load cost.)
__device__ __forceinline__ uint32_t swz(int r, int c) {
    return (uint32_t)(r * 64 + ((c ^ ((r >> 1) & 3)) << 4));
}

__device__ __forceinline__ void load_tile_pair(uint32_t sbase, const __half* gA,
                                               const __half* gB, int tid) {
    #pragma unroll
    for (int h = 0; h < 2; h++) {
        int idx = tid + h * 256;                      // 512 x 16B chunks per operand
        int r = idx >> 2, c = idx & 3;
        cp16(sbase + swz(r, c), gA + (size_t)r * INDIM + c * 8);
        cp16(sbase + TILE_BYTES + swz(r, c), gB + (size_t)r * INDIM + c * 8);
    }
}

__global__ void __launch_bounds__(256, 2) k_gemm() {
    extern __shared__ char dsm[];
    const uint32_t sb = smem_u32(dsm);

    const int tid = threadIdx.x;
    const int wid = tid >> 5, lane = tid & 31;
    const int wm = wid & 3, wn = wid >> 2;            // 4 x 2 warp grid
    const int warp_m0 = wm * 32, warp_n0 = wn * 64;

    // L2-friendly mapping: 16 consecutive bids share the same m-block
    const int m0 = (int)(blockIdx.x >> 4) * BM;
    const int n0 = (int)(blockIdx.x & 15) * BN;

    const __half* gA0 = g_xh + (size_t)m0 * INDIM;
    const __half* gB0 = g_wh + (size_t)n0 * INDIM;

    // per-lane ldmatrix offsets (within a stage)
    uint32_t a_off[2][2];
    #pragma unroll
    for (int mt = 0; mt < 2; mt++)
        #pragma unroll
        for (int ks = 0; ks < 2; ks++) {
            int r = warp_m0 + mt * 16 + (lane & 15);
            int c = ks * 2 + (lane >> 4);
            a_off[mt][ks] = swz(r, c);
        }
    uint32_t b_off[4][2];
    #pragma unroll
    for (int nt = 0; nt < 4; nt++)
        #pragma unroll
        for (int ks = 0; ks < 2; ks++) {
            int r = warp_n0 + nt * 16 + ((lane >> 4) << 3) + (lane & 7);
            int c = ks * 2 + ((lane >> 3) & 1);
            b_off[nt][ks] = (uint32_t)TILE_BYTES + swz(r, c);
        }

    float acc[2][8][4];
    #pragma unroll
    for (int mt = 0; mt < 2; mt++)
        #pragma unroll
        for (int nt = 0; nt < 8; nt++)
            #pragma unroll
            for (int j = 0; j < 4; j++) acc[mt][nt][j] = 0.f;

    // prologue: stages 0..STAGES-2
    #pragma unroll
    for (int s = 0; s < STAGES - 1; s++) {
        load_tile_pair(sb + s * STAGE_BYTES, gA0 + s * BK, gB0 + s * BK, tid);
        CP_COMMIT();
    }

    for (int kt = 0; kt < NK; kt++) {
        CP_WAIT(STAGES - 2);
        __syncthreads();

        int pf = kt + STAGES - 1;
        if (pf < NK)
            load_tile_pair(sb + (pf % STAGES) * STAGE_BYTES,
                           gA0 + pf * BK, gB0 + pf * BK, tid);
        CP_COMMIT();

        const uint32_t st = sb + (kt % STAGES) * STAGE_BYTES;
        #pragma unroll
        for (int ks = 0; ks < 2; ks++) {
            uint32_t a[2][4], b[4][4];
            #pragma unroll
            for (int mt = 0; mt < 2; mt++) ldsm_x4(a[mt], st + a_off[mt][ks]);
            #pragma unroll
            for (int nt = 0; nt < 4; nt++) ldsm_x4(b[nt], st + b_off[nt][ks]);
            #pragma unroll
            for (int mt = 0; mt < 2; mt++)
                #pragma unroll
                for (int nt = 0; nt < 4; nt++) {
                    mma16816(acc[mt][2 * nt],     a[mt], &b[nt][0]);
                    mma16816(acc[mt][2 * nt + 1], a[mt], &b[nt][2]);
                }
        }
    }
    CP_WAIT(0);          // retire trailing (empty) cp groups before smem reuse

    // ---- fused BN statistics, register-flat ----
    __syncthreads();
    float* sred = (float*)dsm;               // reuse pipeline smem: [8][64][2]
    #pragma unroll
    for (int nt = 0; nt < 8; nt++) {
        float e = 0.f, o = 0.f, x2e = 0.f, x2o = 0.f;
        #pragma unroll
        for (int mt = 0; mt < 2; mt++) {
            float a0 = acc[mt][nt][0], a1 = acc[mt][nt][1];
            float a2 = acc[mt][nt][2], a3 = acc[mt][nt][3];
            e += a0 + a2;  o += a1 + a3;
            x2e += a0 * a0 + a2 * a2;  x2o += a1 * a1 + a3 * a3;
        }
        #pragma unroll
        for (int d = 16; d >= 4; d >>= 1) {   // reduce over the 8 g-lanes
            e   += __shfl_xor_sync(0xffffffff, e, d);
            o   += __shfl_xor_sync(0xffffffff, o, d);
            x2e += __shfl_xor_sync(0xffffffff, x2e, d);
            x2o += __shfl_xor_sync(0xffffffff, x2o, d);
        }
        if (lane < 4) {                       // lane == tg, g == 0
            int lc = nt * 8 + lane * 2;
            sred[(wid * 64 + lc) * 2 + 0]     = e;
            sred[(wid * 64 + lc) * 2 + 1]     = x2e;
            sred[(wid * 64 + lc + 1) * 2 + 0] = o;
            sred[(wid * 64 + lc + 1) * 2 + 1] = x2o;
        }
    }
    __syncthreads();

    // cross-warp reduce (4 wm-warps share each column) + one atomic per col/stat
    {
        int col = tid >> 1, stt = tid & 1;   // 128 cols x 2 stats
        int wbase = (col >> 6) * 4, lc = col & 63;
        float v = sred[((wbase + 0) * 64 + lc) * 2 + stt]
                + sred[((wbase + 1) * 64 + lc) * 2 + stt]
                + sred[((wbase + 2) * 64 + lc) * 2 + stt]
                + sred[((wbase + 3) * 64 + lc) * 2 + stt];
        atomicAdd((stt ? g_cq : g_cs) + n0 + col, v);
    }

    // ---- y-write last, in fp16, no barrier after ----
    const int g = lane >> 2, tg = lane & 3;
    #pragma unroll
    for (int mt = 0; mt < 2; mt++) {
        int mrow = m0 + warp_m0 + mt * 16 + g;
        #pragma unroll
        for (int nt = 0; nt < 8; nt++) {
            int col = n0 + warp_n0 + nt * 8 + tg * 2;
            __half2* p0 = (__half2*)(g_yh + (size_t)mrow * OUTDIM + col);
            __half2* p1 = (__half2*)(g_yh + (size_t)(mrow + 8) * OUTDIM + col);
            *p0 = __floats2half2_rn(acc[mt][nt][0], acc[mt][nt][1]);
            *p1 = __floats2half2_rn(acc[mt][nt][2], acc[mt][nt][3]);
        }
    }
}

__global__ void k_params(const float* __restrict__ gamma, const float* __restrict__ beta) {
    int o = blockIdx.x * blockDim.x + threadIdx.x;
    if (o < OUTDIM) {
        float inv_n = 1.f / (float)BDIM;
        float mean = g_cs[o] * inv_n;
        float var  = g_cq[o] * inv_n - mean * mean;
        float sc = gamma[o] * rsqrtf(var + 1e-5f);
        g_scale[o] = sc;
        g_bias[o]  = beta[o] - mean * sc;
    }
}

// ---------------- normalize + ReLU: fp16 y -> fp32 out ----------------
__global__ void k_norm(float* __restrict__ out) {
    int i = blockIdx.x * blockDim.x + threadIdx.x;   // over 4194304 8-col chunks
    int c8 = i & (OUTDIM / 8 - 1);
    uint4 v = ((const uint4*)g_yh)[i];
    const uint32_t u[4] = {v.x, v.y, v.z, v.w};
    float4 sc0 = ((const float4*)g_scale)[2 * c8];
    float4 sc1 = ((const float4*)g_scale)[2 * c8 + 1];
    float4 bs0 = ((const float4*)g_bias)[2 * c8];
    float4 bs1 = ((const float4*)g_bias)[2 * c8 + 1];
    float2 f0 = __half22float2(*(const __half2*)&u[0]);
    float2 f1 = __half22float2(*(const __half2*)&u[1]);
    float2 f2 = __half22float2(*(const __half2*)&u[2]);
    float2 f3 = __half22float2(*(const __half2*)&u[3]);
    float4 o0, o1;
    o0.x = fmaxf(fmaf(f0.x, sc0.x, bs0.x), 0.f);
    o0.y = fmaxf(fmaf(f0.y, sc0.y, bs0.y), 0.f);
    o0.z = fmaxf(fmaf(f1.x, sc0.z, bs0.z), 0.f);
    o0.w = fmaxf(fmaf(f1.y, sc0.w, bs0.w), 0.f);
    o1.x = fmaxf(fmaf(f2.x, sc1.x, bs1.x), 0.f);
    o1.y = fmaxf(fmaf(f2.y, sc1.y, bs1.y), 0.f);
    o1.z = fmaxf(fmaf(f3.x, sc1.z, bs1.z), 0.f);
    o1.w = fmaxf(fmaf(f3.y, sc1.w, bs1.w), 0.f);
    ((float4*)out)[2 * (size_t)i]     = o0;
    ((float4*)out)[2 * (size_t)i + 1] = o1;
}

// ---------------- launch ----------------
extern "C" void kernel_launch(void* const* d_in, const int* in_sizes, int n_in,
                              void* d_out, int out_size) {
    const float* x     = (const float*)d_in[0];
    const float* w     = (const float*)d_in[1];
    const float* gamma = (const float*)d_in[2];
    const float* beta  = (const float*)d_in[3];
    float* out = (float*)d_out;

    static bool attr_set = false;
    if (!attr_set) {
        cudaFuncSetAttribute(k_gemm, cudaFuncAttributeMaxDynamicSharedMemorySize, DSMEM);
        attr_set = true;
    }

    k_convert_x<<<(BDIM * INDIM / 4) / 256, 256>>>(x);
    k_convert_w<<<(OUTDIM * INDIM / 4) / 256, 256>>>(w);

    k_gemm<<<(BDIM / BM) * (OUTDIM / BN), 256, DSMEM>>>();

    k_params<<<(OUTDIM + 255) / 256, 256>>>(gamma, beta);
    k_norm<<<(BDIM * OUTDIM / 8) / 256, 256>>>(out);
}

// round 17
// speedup vs baseline: 1.4532x; 1.0104x over previous
#include <cuda_runtime.h>
#include <cuda_fp16.h>
#include <cstdint>

#define BDIM 16384
#define INDIM 2048
#define OUTDIM 2048

// ---------------- scratch (static device globals; no allocation) ----------------
__device__ __half g_xh[(size_t)BDIM * INDIM];    // x in fp16
__device__ __half g_wh[(size_t)OUTDIM * INDIM];  // sign(W) in fp16 (+1/-1 exact)
__device__ __half g_yh[(size_t)BDIM * OUTDIM];   // y intermediate in fp16
__device__ float  g_cs[OUTDIM];                  // column sums of y
__device__ float  g_cq[OUTDIM];                  // column sums of y^2
__device__ float  g_scale[OUTDIM];
__device__ float  g_bias[OUTDIM];

// ---------------- helpers ----------------
__device__ __forceinline__ uint32_t smem_u32(const void* p) {
    uint32_t a;
    asm("{ .reg .u64 t; cvta.to.shared.u64 t, %1; cvt.u32.u64 %0, t; }" : "=r"(a) : "l"(p));
    return a;
}
__device__ __forceinline__ void cp16(uint32_t s, const void* g) {
    asm volatile("cp.async.cg.shared.global [%0], [%1], 16;" :: "r"(s), "l"(g) : "memory");
}
#define CP_COMMIT() asm volatile("cp.async.commit_group;" ::: "memory")
#define CP_WAIT(n)  asm volatile("cp.async.wait_group %0;" :: "n"(n) : "memory")

__device__ __forceinline__ void ldsm_x4(uint32_t* r, uint32_t addr) {
    asm volatile("ldmatrix.sync.aligned.m8n8.x4.shared.b16 {%0,%1,%2,%3}, [%4];"
                 : "=r"(r[0]), "=r"(r[1]), "=r"(r[2]), "=r"(r[3]) : "r"(addr));
}
__device__ __forceinline__ void mma16816(float* c, const uint32_t* a, const uint32_t* b) {
    asm volatile(
        "mma.sync.aligned.m16n8k16.row.col.f32.f16.f16.f32 "
        "{%0,%1,%2,%3}, {%4,%5,%6,%7}, {%8,%9}, {%0,%1,%2,%3};"
        : "+f"(c[0]), "+f"(c[1]), "+f"(c[2]), "+f"(c[3])
        : "r"(a[0]), "r"(a[1]), "r"(a[2]), "r"(a[3]), "r"(b[0]), "r"(b[1]));
}

// ---------------- conversion kernels ----------------
__global__ void k_convert_x(const float* __restrict__ x) {
    int i = blockIdx.x * blockDim.x + threadIdx.x;   // over 8388608 float4s
    float4 v = ((const float4*)x)[i];
    ((__half2*)g_xh)[2 * (size_t)i]     = __floats2half2_rn(v.x, v.y);
    ((__half2*)g_xh)[2 * (size_t)i + 1] = __floats2half2_rn(v.z, v.w);
}

__global__ void k_convert_w(const float* __restrict__ w) {
    int i = blockIdx.x * blockDim.x + threadIdx.x;   // over 1048576 float4s
    float4 v = ((const float4*)w)[i];
    float s0 = (v.x >= 0.f) ? 1.f : -1.f;
    float s1 = (v.y >= 0.f) ? 1.f : -1.f;
    float s2 = (v.z >= 0.f) ? 1.f : -1.f;
    float s3 = (v.w >= 0.f) ? 1.f : -1.f;
    ((__half2*)g_wh)[2 * (size_t)i]     = __floats2half2_rn(s0, s1);
    ((__half2*)g_wh)[2 * (size_t)i + 1] = __floats2half2_rn(s2, s3);
    if (i < OUTDIM) { g_cs[i] = 0.f; g_cq[i] = 0.f; }   // reset stats every call
}

// ---------------- HMMA GEMM + fused BN stats (y stored fp16) ----------------
// CTA tile 128x128, BK=32, 5 cp.async stages, 8 warps (warp tile 32x64).
static constexpr int BM = 128, BN = 128, BK = 32;
static constexpr int STAGES = 5;
static constexpr int NK = INDIM / BK;                 // 64
static constexpr int TILE_BYTES = BM * BK * 2;        // 8192 per operand
static constexpr int STAGE_BYTES = 2 * TILE_BYTES;    // 16384
static constexpr int DSMEM = STAGES * STAGE_BYTES;    // 81920

// Conflict-free swizzle (see R16): permute 16B chunks on (r>>1)&3 so each
// ldmatrix phase (8 consecutive rows, one chunk column) hits all 32 banks once.
__device__ __forceinline__ uint32_t swz(int r, int c) {
    return (uint32_t)(r * 64 + ((c ^ ((r >> 1) & 3)) << 4));
}

__device__ __forceinline__ void load_tile_pair(uint32_t sbase, const __half* gA,
                                               const __half* gB, int tid) {
    #pragma unroll
    for (int h = 0; h < 2; h++) {
        int idx = tid + h * 256;                      // 512 x 16B chunks per operand
        int r = idx >> 2, c = idx & 3;
        cp16(sbase + swz(r, c), gA + (size_t)r * INDIM + c * 8);
        cp16(sbase + TILE_BYTES + swz(r, c), gB + (size_t)r * INDIM + c * 8);
    }
}

__global__ void __launch_bounds__(256, 2) k_gemm() {
    extern __shared__ char dsm[];
    const uint32_t sb = smem_u32(dsm);

    const int tid = threadIdx.x;
    const int wid = tid >> 5, lane = tid & 31;
    const int wm = wid & 3, wn = wid >> 2;            // 4 x 2 warp grid
    const int warp_m0 = wm * 32, warp_n0 = wn * 64;

    // L2-friendly mapping: 16 consecutive bids share the same m-block
    const int m0 = (int)(blockIdx.x >> 4) * BM;
    const int n0 = (int)(blockIdx.x & 15) * BN;

    const __half* gA0 = g_xh + (size_t)m0 * INDIM;
    const __half* gB0 = g_wh + (size_t)n0 * INDIM;

    // per-lane ldmatrix offsets (within a stage)
    uint32_t a_off[2][2];
    #pragma unroll
    for (int mt = 0; mt < 2; mt++)
        #pragma unroll
        for (int ks = 0; ks < 2; ks++) {
            int r = warp_m0 + mt * 16 + (lane & 15);
            int c = ks * 2 + (lane >> 4);
            a_off[mt][ks] = swz(r, c);
        }
    uint32_t b_off[4][2];
    #pragma unroll
    for (int nt = 0; nt < 4; nt++)
        #pragma unroll
        for (int ks = 0; ks < 2; ks++) {
            int r = warp_n0 + nt * 16 + ((lane >> 4) << 3) + (lane & 7);
            int c = ks * 2 + ((lane >> 3) & 1);
            b_off[nt][ks] = (uint32_t)TILE_BYTES + swz(r, c);
        }

    float acc[2][8][4];
    #pragma unroll
    for (int mt = 0; mt < 2; mt++)
        #pragma unroll
        for (int nt = 0; nt < 8; nt++)
            #pragma unroll
            for (int j = 0; j < 4; j++) acc[mt][nt][j] = 0.f;

    // prologue: stages 0..STAGES-2
    #pragma unroll
    for (int s = 0; s < STAGES - 1; s++) {
        load_tile_pair(sb + s * STAGE_BYTES, gA0 + s * BK, gB0 + s * BK, tid);
        CP_COMMIT();
    }

    for (int kt = 0; kt < NK; kt++) {
        CP_WAIT(STAGES - 2);
        __syncthreads();

        const uint32_t st = sb + (kt % STAGES) * STAGE_BYTES;

        // ---- ks = 0: fragment loads FIRST (start their latency chains) ----
        uint32_t a[2][4], b[4][4];
        #pragma unroll
        for (int mt = 0; mt < 2; mt++) ldsm_x4(a[mt], st + a_off[mt][0]);
        #pragma unroll
        for (int nt = 0; nt < 4; nt++) ldsm_x4(b[nt], st + b_off[nt][0]);

        // ---- prefetch issued here: overlaps the ldsm->MMA dependency window ----
        int pf = kt + STAGES - 1;
        if (pf < NK)
            load_tile_pair(sb + (pf % STAGES) * STAGE_BYTES,
                           gA0 + pf * BK, gB0 + pf * BK, tid);
        CP_COMMIT();

        // ---- ks = 0 MMAs ----
        #pragma unroll
        for (int mt = 0; mt < 2; mt++)
            #pragma unroll
            for (int nt = 0; nt < 4; nt++) {
                mma16816(acc[mt][2 * nt],     a[mt], &b[nt][0]);
                mma16816(acc[mt][2 * nt + 1], a[mt], &b[nt][2]);
            }

        // ---- ks = 1 ----
        #pragma unroll
        for (int mt = 0; mt < 2; mt++) ldsm_x4(a[mt], st + a_off[mt][1]);
        #pragma unroll
        for (int nt = 0; nt < 4; nt++) ldsm_x4(b[nt], st + b_off[nt][1]);
        #pragma unroll
        for (int mt = 0; mt < 2; mt++)
            #pragma unroll
            for (int nt = 0; nt < 4; nt++) {
                mma16816(acc[mt][2 * nt],     a[mt], &b[nt][0]);
                mma16816(acc[mt][2 * nt + 1], a[mt], &b[nt][2]);
            }
    }
    CP_WAIT(0);          // retire trailing (empty) cp groups before smem reuse

    // ---- fused BN statistics, register-flat ----
    __syncthreads();
    float* sred = (float*)dsm;               // reuse pipeline smem: [8][64][2]
    #pragma unroll
    for (int nt = 0; nt < 8; nt++) {
        float e = 0.f, o = 0.f, x2e = 0.f, x2o = 0.f;
        #pragma unroll
        for (int mt = 0; mt < 2; mt++) {
            float a0 = acc[mt][nt][0], a1 = acc[mt][nt][1];
            float a2 = acc[mt][nt][2], a3 = acc[mt][nt][3];
            e += a0 + a2;  o += a1 + a3;
            x2e += a0 * a0 + a2 * a2;  x2o += a1 * a1 + a3 * a3;
        }
        #pragma unroll
        for (int d = 16; d >= 4; d >>= 1) {   // reduce over the 8 g-lanes
            e   += __shfl_xor_sync(0xffffffff, e, d);
            o   += __shfl_xor_sync(0xffffffff, o, d);
            x2e += __shfl_xor_sync(0xffffffff, x2e, d);
            x2o += __shfl_xor_sync(0xffffffff, x2o, d);
        }
        if (lane < 4) {                       // lane == tg, g == 0
            int lc = nt * 8 + lane * 2;
            sred[(wid * 64 + lc) * 2 + 0]     = e;
            sred[(wid * 64 + lc) * 2 + 1]     = x2e;
            sred[(wid * 64 + lc + 1) * 2 + 0] = o;
            sred[(wid * 64 + lc + 1) * 2 + 1] = x2o;
        }
    }
    __syncthreads();

    // cross-warp reduce (4 wm-warps share each column) + one atomic per col/stat
    {
        int col = tid >> 1, stt = tid & 1;   // 128 cols x 2 stats
        int wbase = (col >> 6) * 4, lc = col & 63;
        float v = sred[((wbase + 0) * 64 + lc) * 2 + stt]
                + sred[((wbase + 1) * 64 + lc) * 2 + stt]
                + sred[((wbase + 2) * 64 + lc) * 2 + stt]
                + sred[((wbase + 3) * 64 + lc) * 2 + stt];
        atomicAdd((stt ? g_cq : g_cs) + n0 + col, v);
    }

    // ---- y-write last, in fp16, no barrier after ----
    const int g = lane >> 2, tg = lane & 3;
    #pragma unroll
    for (int mt = 0; mt < 2; mt++) {
        int mrow = m0 + warp_m0 + mt * 16 + g;
        #pragma unroll
        for (int nt = 0; nt < 8; nt++) {
            int col = n0 + warp_n0 + nt * 8 + tg * 2;
            __half2* p0 = (__half2*)(g_yh + (size_t)mrow * OUTDIM + col);
            __half2* p1 = (__half2*)(g_yh + (size_t)(mrow + 8) * OUTDIM + col);
            *p0 = __floats2half2_rn(acc[mt][nt][0], acc[mt][nt][1]);
            *p1 = __floats2half2_rn(acc[mt][nt][2], acc[mt][nt][3]);
        }
    }
}

__global__ void k_params(const float* __restrict__ gamma, const float* __restrict__ beta) {
    int o = blockIdx.x * blockDim.x + threadIdx.x;
    if (o < OUTDIM) {
        float inv_n = 1.f / (float)BDIM;
        float mean = g_cs[o] * inv_n;
        float var  = g_cq[o] * inv_n - mean * mean;
        float sc = gamma[o] * rsqrtf(var + 1e-5f);
        g_scale[o] = sc;
        g_bias[o]  = beta[o] - mean * sc;
    }
}

// ---------------- normalize + ReLU: fp16 y -> fp32 out ----------------
__global__ void k_norm(float* __restrict__ out) {
    int i = blockIdx.x * blockDim.x + threadIdx.x;   // over 4194304 8-col chunks
    int c8 = i & (OUTDIM / 8 - 1);
    uint4 v = ((const uint4*)g_yh)[i];
    const uint32_t u[4] = {v.x, v.y, v.z, v.w};
    float4 sc0 = ((const float4*)g_scale)[2 * c8];
    float4 sc1 = ((const float4*)g_scale)[2 * c8 + 1];
    float4 bs0 = ((const float4*)g_bias)[2 * c8];
    float4 bs1 = ((const float4*)g_bias)[2 * c8 + 1];
    float2 f0 = __half22float2(*(const __half2*)&u[0]);
    float2 f1 = __half22float2(*(const __half2*)&u[1]);
    float2 f2 = __half22float2(*(const __half2*)&u[2]);
    float2 f3 = __half22float2(*(const __half2*)&u[3]);
    float4 o0, o1;
    o0.x = fmaxf(fmaf(f0.x, sc0.x, bs0.x), 0.f);
    o0.y = fmaxf(fmaf(f0.y, sc0.y, bs0.y), 0.f);
    o0.z = fmaxf(fmaf(f1.x, sc0.z, bs0.z), 0.f);
    o0.w = fmaxf(fmaf(f1.y, sc0.w, bs0.w), 0.f);
    o1.x = fmaxf(fmaf(f2.x, sc1.x, bs1.x), 0.f);
    o1.y = fmaxf(fmaf(f2.y, sc1.y, bs1.y), 0.f);
    o1.z = fmaxf(fmaf(f3.x, sc1.z, bs1.z), 0.f);
    o1.w = fmaxf(fmaf(f3.y, sc1.w, bs1.w), 0.f);
    ((float4*)out)[2 * (size_t)i]     = o0;
    ((float4*)out)[2 * (size_t)i + 1] = o1;
}

// ---------------- launch ----------------
extern "C" void kernel_launch(void* const* d_in, const int* in_sizes, int n_in,
                              void* d_out, int out_size) {
    const float* x     = (const float*)d_in[0];
    const float* w     = (const float*)d_in[1];
    const float* gamma = (const float*)d_in[2];
    const float* beta  = (const float*)d_in[3];
    float* out = (float*)d_out;

    static bool attr_set = false;
    if (!attr_set) {
        cudaFuncSetAttribute(k_gemm, cudaFuncAttributeMaxDynamicSharedMemorySize, DSMEM);
        attr_set = true;
    }

    k_convert_x<<<(BDIM * INDIM / 4) / 256, 256>>>(x);
    k_convert_w<<<(OUTDIM * INDIM / 4) / 256, 256>>>(w);

    k_gemm<<<(BDIM / BM) * (OUTDIM / BN), 256, DSMEM>>>();

    k_params<<<(OUTDIM + 255) / 256, 256>>>(gamma, beta);
    k_norm<<<(BDIM * OUTDIM / 8) / 256, 256>>>(out);
}